// round 16
// baseline (speedup 1.0000x reference)
#include <cuda_runtime.h>
#include <cuda_fp16.h>
#include <math.h>
#include <stdint.h>

// Problem constants
#define BATCH 4
#define TLEN  8192
#define EMB   1024
#define DH    64
#define MF    8
#define NJ    80          // 8 p_q + 8 p_k + 64 v
#define TM    128         // tokens per phase-1 tile (MMA M)
#define KC    64          // K per staged chunk (4 ks-blocks of 16)
#define NCHUNK (EMB/KC)   // 16
#define NTILE ((BATCH*TLEN)/TM)   // 256
#define NFEAT (2*MF)
#define INV_SQRT_M 0.35355339059327376f

// ---- device scratch (no allocations allowed) ----
__device__ __half g_WBh[EMB*NJ];          // folded W [e][j] fp16 hi
__device__ __half g_WBl[EMB*NJ];          // fp16 lo residual (cols 0..15 used)
__device__ float g_bias[NJ];
__device__ float g_qP[BATCH*TLEN*NFEAT];  // finished q features (2 MB)
__device__ float g_Spart[NTILE*NFEAT*DH];
__device__ float g_S[BATCH*NFEAT*DH];

// ---- smem stage layout (KC=64) ----
#define OFF_ALO 18432      // a_hi[128][72] half, 144 B rows = 18432 B
#define OFF_BHI 36864      // a_lo same size
#define OFF_BLO 48128      // b_hi[64][88] half = 11264 B
#define STAGE_BYTES 51200  // b_lo[64][24] half = 3072 B
#define DYN_BYTES (2 * STAGE_BYTES)   // 102400; 2 CTAs/SM -> 200 KB < 228 KB

// ---- epilogue panel layout (aliases stage smem after final sync) ----
#define P_KPH 0            // Kp hi [128][24] half, 48 B rows (6144 B)
#define P_KPL 6144
#define P_VH  12288        // V hi [128][72] half, 144 B rows (18432 B)
#define P_VL  30720        // ends 49152 < 51200

// ---- helpers ----
__device__ __forceinline__ uint32_t smem_u32(const void* p) {
    uint32_t a;
    asm("{ .reg .u64 t; cvta.to.shared.u64 t, %1; cvt.u32.u64 %0, t; }" : "=r"(a) : "l"(p));
    return a;
}
__device__ __forceinline__ void ldsm_x4(uint32_t* r, uint32_t addr) {
    asm volatile("ldmatrix.sync.aligned.m8n8.x4.shared.b16 {%0,%1,%2,%3}, [%4];"
        : "=r"(r[0]), "=r"(r[1]), "=r"(r[2]), "=r"(r[3]) : "r"(addr));
}
__device__ __forceinline__ void ldsm_x4_t(uint32_t* r, uint32_t addr) {
    asm volatile("ldmatrix.sync.aligned.m8n8.x4.trans.shared.b16 {%0,%1,%2,%3}, [%4];"
        : "=r"(r[0]), "=r"(r[1]), "=r"(r[2]), "=r"(r[3]) : "r"(addr));
}
__device__ __forceinline__ void mma_f16(float* c, const uint32_t* a, const uint32_t* b) {
    asm volatile("mma.sync.aligned.m16n8k16.row.col.f32.f16.f16.f32 "
        "{%0,%1,%2,%3}, {%4,%5,%6,%7}, {%8,%9}, {%0,%1,%2,%3};"
        : "+f"(c[0]), "+f"(c[1]), "+f"(c[2]), "+f"(c[3])
        : "r"(a[0]), "r"(a[1]), "r"(a[2]), "r"(a[3]), "r"(b[0]), "r"(b[1]));
}
__device__ __forceinline__ void split_pack(float vx, float vy, uint32_t& hi, uint32_t& lo) {
    __half2 h = __floats2half2_rn(vx, vy);
    float2 hf = __half22float2(h);
    __half2 l = __floats2half2_rn(vx - hf.x, vy - hf.y);
    hi = *reinterpret_cast<uint32_t*>(&h);
    lo = *reinterpret_cast<uint32_t*>(&l);
}
__device__ __forceinline__ void cp_async16(uint32_t smem_addr, const void* gptr) {
    asm volatile("cp.async.ca.shared.global [%0], [%1], 16;"
        :: "r"(smem_addr), "l"(gptr) : "memory");
}
#define CP_COMMIT() asm volatile("cp.async.commit_group;" ::: "memory")
#define CP_WAIT0()  asm volatile("cp.async.wait_group 0;" ::: "memory")

// ============================================================
// prep: fold Wq@w, Wk@w + Wv into fp16 hi/lo [e][j]; biases.
// ============================================================
__global__ void prep_kernel(const float* __restrict__ w,
                            const float* __restrict__ Wq, const float* __restrict__ bq,
                            const float* __restrict__ Wk, const float* __restrict__ bk,
                            const float* __restrict__ Wv, const float* __restrict__ bv) {
    int g = blockIdx.x * blockDim.x + threadIdx.x;
    if (g < NJ) {
        float bb;
        if (g < MF) {
            float s0 = 0.f, s1 = 0.f, s2 = 0.f, s3 = 0.f;
            for (int d = 0; d < DH; d += 4) {
                s0 += bq[d]     * w[(d)    *MF + g];
                s1 += bq[d + 1] * w[(d + 1)*MF + g];
                s2 += bq[d + 2] * w[(d + 2)*MF + g];
                s3 += bq[d + 3] * w[(d + 3)*MF + g];
            }
            bb = (s0 + s1) + (s2 + s3);
        } else if (g < 2*MF) {
            int jj = g - MF;
            float s0 = 0.f, s1 = 0.f, s2 = 0.f, s3 = 0.f;
            for (int d = 0; d < DH; d += 4) {
                s0 += bk[d]     * w[(d)    *MF + jj];
                s1 += bk[d + 1] * w[(d + 1)*MF + jj];
                s2 += bk[d + 2] * w[(d + 2)*MF + jj];
                s3 += bk[d + 3] * w[(d + 3)*MF + jj];
            }
            bb = (s0 + s1) + (s2 + s3);
        } else {
            bb = bv[g - 2*MF];
        }
        g_bias[g] = bb;
    }
    if (g >= EMB*NJ) return;
    int e = g / NJ;
    int j = g - e*NJ;
    float val;
    if (j < MF) {
        float s0 = 0.f, s1 = 0.f, s2 = 0.f, s3 = 0.f;
        for (int d = 0; d < DH; d += 4) {
            s0 += Wq[e*DH + d]     * w[(d)    *MF + j];
            s1 += Wq[e*DH + d + 1] * w[(d + 1)*MF + j];
            s2 += Wq[e*DH + d + 2] * w[(d + 2)*MF + j];
            s3 += Wq[e*DH + d + 3] * w[(d + 3)*MF + j];
        }
        val = (s0 + s1) + (s2 + s3);
    } else if (j < 2*MF) {
        int jj = j - MF;
        float s0 = 0.f, s1 = 0.f, s2 = 0.f, s3 = 0.f;
        for (int d = 0; d < DH; d += 4) {
            s0 += Wk[e*DH + d]     * w[(d)    *MF + jj];
            s1 += Wk[e*DH + d + 1] * w[(d + 1)*MF + jj];
            s2 += Wk[e*DH + d + 2] * w[(d + 2)*MF + jj];
            s3 += Wk[e*DH + d + 3] * w[(d + 3)*MF + jj];
        }
        val = (s0 + s1) + (s2 + s3);
    } else {
        val = Wv[e*DH + (j - 2*MF)];
    }
    __half h = __float2half_rn(val);
    g_WBh[g] = h;
    g_WBl[g] = __float2half_rn(val - __half2float(h));
}

// ============================================================
// phase 1: pipelined HMMA fp16 GEMM [128 x 80], KC=64 rounds,
// B staged via cp.async (no regs/STS); MMA-based epilogue.
// p-cols (0..15): 3-term split; v-cols (16..79): 1-term hi*hi
// ============================================================
__global__ __launch_bounds__(256, 2) void phase1_kernel(const float* __restrict__ x) {
    extern __shared__ char smc[];
    const int tid  = threadIdx.x;
    const int lane = tid & 31;
    const int w    = tid >> 5;
    const int tile = blockIdx.x;
    const float* xrow = x + (size_t)tile * TM * EMB;
    const uint32_t sbase = smem_u32(smc);

    // ldsm offsets within a stage
    const uint32_t aOffHi = (uint32_t)((16*w + (lane & 15)) * 144 + ((lane >> 4) * 8) * 2);
    const uint32_t bOffHi = (uint32_t)(OFF_BHI + (lane & 15) * 176 + ((lane >> 4) * 8) * 2);
    const uint32_t bOffLo = (uint32_t)(OFF_BLO + (lane & 15) * 48  + ((lane >> 4) * 8) * 2);

    // A staging indices: 2048 float4 / 256 threads = 8 each
    const int sa_tok = tid >> 4;               // + i*16
    const int sa_k4  = (tid & 15) << 2;

    float acc[10][4];
    #pragma unroll
    for (int nt = 0; nt < 10; nt++)
        #pragma unroll
        for (int i = 0; i < 4; i++) acc[nt][i] = 0.f;

    // ---- B cp.async issue helper indices ----
    // b_hi: 640 x 16B (64 rows x 10), 3 iters; b_lo: 128 x 16B (64 rows x 2)
    // ---- prologue: stage chunk 0 into stage 0 ----
    {
        char* sb = smc;
        #pragma unroll
        for (int i = 0; i < 8; i++) {
            int tok = sa_tok + i * 16;
            float4 v = *reinterpret_cast<const float4*>(xrow + (size_t)tok * EMB + sa_k4);
            uint32_t h0, l0, h1, l1;
            split_pack(v.x, v.y, h0, l0);
            split_pack(v.z, v.w, h1, l1);
            uint32_t off = (uint32_t)(tok * 144 + sa_k4 * 2);
            *reinterpret_cast<uint2*>(sb + off)           = make_uint2(h0, h1);
            *reinterpret_cast<uint2*>(sb + OFF_ALO + off) = make_uint2(l0, l1);
        }
        #pragma unroll
        for (int i = 0; i < 3; i++) {
            int idx = tid + i * 256;
            if (idx < 640) {
                int k = idx / 10, jp = idx - k * 10;
                cp_async16(sbase + OFF_BHI + k * 176 + jp * 16,
                           &g_WBh[(size_t)k * NJ + jp * 8]);
            }
        }
        if (tid < 128) {
            int k = tid >> 1, j = tid & 1;
            cp_async16(sbase + OFF_BLO + k * 48 + j * 16,
                       &g_WBl[(size_t)k * NJ + j * 8]);
        }
        CP_COMMIT();
        CP_WAIT0();
    }
    __syncthreads();

    // ---- pipelined main loop (16 rounds) ----
    for (int c = 0; c < NCHUNK; c++) {
        const uint32_t sOff = (uint32_t)((c & 1) * STAGE_BYTES);
        const int nxt = c + 1;
        const uint32_t nOffs = (uint32_t)((nxt & 1) * STAGE_BYTES);

        // 1) issue cp.async for next chunk's B + prefetch next A into regs
        float4 va[8];
        if (nxt < NCHUNK) {
            const int ko = nxt * KC;
            #pragma unroll
            for (int i = 0; i < 3; i++) {
                int idx = tid + i * 256;
                if (idx < 640) {
                    int k = idx / 10, jp = idx - k * 10;
                    cp_async16(sbase + nOffs + OFF_BHI + k * 176 + jp * 16,
                               &g_WBh[(size_t)(ko + k) * NJ + jp * 8]);
                }
            }
            if (tid < 128) {
                int k = tid >> 1, j = tid & 1;
                cp_async16(sbase + nOffs + OFF_BLO + k * 48 + j * 16,
                           &g_WBl[(size_t)(ko + k) * NJ + j * 8]);
            }
            CP_COMMIT();
            #pragma unroll
            for (int i = 0; i < 8; i++) {
                int tok = sa_tok + i * 16;
                va[i] = *reinterpret_cast<const float4*>(xrow + (size_t)tok * EMB + ko + sa_k4);
            }
        }

        // 2) compute chunk c from stage (c&1): 4 ks-blocks
        const uint32_t aHiAddr = sbase + sOff + aOffHi;
        const uint32_t aLoAddr = aHiAddr + OFF_ALO;
        const uint32_t bHiAddr = sbase + sOff + bOffHi;
        const uint32_t bLoAddr = sbase + sOff + bOffLo;
        #pragma unroll
        for (int ks = 0; ks < 4; ks++) {
            uint32_t Ah[4], Al[4];
            ldsm_x4(Ah, aHiAddr + ks * 32);
            ldsm_x4(Al, aLoAddr + ks * 32);
            // p-columns: 3-term split
            {
                uint32_t Bh[4], Bl[4];
                ldsm_x4_t(Bh, bHiAddr + ks * 2816);
                ldsm_x4_t(Bl, bLoAddr + ks * 768);
                mma_f16(acc[0], Ah, Bh + 0);
                mma_f16(acc[1], Ah, Bh + 2);
                mma_f16(acc[0], Ah, Bl + 0);
                mma_f16(acc[1], Ah, Bl + 2);
                mma_f16(acc[0], Al, Bh + 0);
                mma_f16(acc[1], Al, Bh + 2);
            }
            // v-columns: 1-term
            #pragma unroll
            for (int np = 1; np < 5; np++) {
                uint32_t Bh[4];
                ldsm_x4_t(Bh, bHiAddr + ks * 2816 + np * 32);
                mma_f16(acc[2*np],     Ah, Bh + 0);
                mma_f16(acc[2*np + 1], Ah, Bh + 2);
            }
        }

        // 3) convert + store next A; wait for B cp.async; barrier
        if (nxt < NCHUNK) {
            char* sb = smc + (nxt & 1) * STAGE_BYTES;
            #pragma unroll
            for (int i = 0; i < 8; i++) {
                int tok = sa_tok + i * 16;
                uint32_t h0, l0, h1, l1;
                split_pack(va[i].x, va[i].y, h0, l0);
                split_pack(va[i].z, va[i].w, h1, l1);
                uint32_t off = (uint32_t)(tok * 144 + sa_k4 * 2);
                *reinterpret_cast<uint2*>(sb + off)           = make_uint2(h0, h1);
                *reinterpret_cast<uint2*>(sb + OFF_ALO + off) = make_uint2(l0, l1);
            }
            CP_WAIT0();
        }
        __syncthreads();
    }

    // ================= MMA-based epilogue =================
    const int t0 = tile * TM;
    const int r0 = 16 * w + (lane >> 2);
    const int cq = 2 * (lane & 3);

    // q-path: acc[0] + bias -> sincos -> g_qP
    {
        float2 b2 = *reinterpret_cast<const float2*>(&g_bias[cq]);
        float sv0, cv0, sv1, cv1;
        sincosf(acc[0][0] + b2.x, &sv0, &cv0);
        sincosf(acc[0][1] + b2.y, &sv1, &cv1);
        float* qp = g_qP + (size_t)(t0 + r0) * NFEAT;
        *reinterpret_cast<float2*>(qp + cq)      = make_float2(cv0*INV_SQRT_M, cv1*INV_SQRT_M);
        *reinterpret_cast<float2*>(qp + MF + cq) = make_float2(sv0*INV_SQRT_M, sv1*INV_SQRT_M);
        sincosf(acc[0][2] + b2.x, &sv0, &cv0);
        sincosf(acc[0][3] + b2.y, &sv1, &cv1);
        qp = g_qP + (size_t)(t0 + r0 + 8) * NFEAT;
        *reinterpret_cast<float2*>(qp + cq)      = make_float2(cv0*INV_SQRT_M, cv1*INV_SQRT_M);
        *reinterpret_cast<float2*>(qp + MF + cq) = make_float2(sv0*INV_SQRT_M, sv1*INV_SQRT_M);
    }
    // k-path: acc[1] + bias -> sincos -> Kp hi/lo panels
    {
        float2 b2 = *reinterpret_cast<const float2*>(&g_bias[8 + cq]);
        #pragma unroll
        for (int half = 0; half < 2; half++) {
            int row = r0 + half * 8;
            float sv0, cv0, sv1, cv1;
            sincosf(acc[1][2*half + 0] + b2.x, &sv0, &cv0);
            sincosf(acc[1][2*half + 1] + b2.y, &sv1, &cv1);
            uint32_t hi, lo;
            split_pack(cv0*INV_SQRT_M, cv1*INV_SQRT_M, hi, lo);
            *reinterpret_cast<uint32_t*>(smc + P_KPH + row*48 + 2*cq) = hi;
            *reinterpret_cast<uint32_t*>(smc + P_KPL + row*48 + 2*cq) = lo;
            split_pack(sv0*INV_SQRT_M, sv1*INV_SQRT_M, hi, lo);
            *reinterpret_cast<uint32_t*>(smc + P_KPH + row*48 + 16 + 2*cq) = hi;
            *reinterpret_cast<uint32_t*>(smc + P_KPL + row*48 + 16 + 2*cq) = lo;
        }
    }
    // v: acc[2..9] + bias -> V hi/lo panels
    #pragma unroll
    for (int nt = 2; nt < 10; nt++) {
        int dcol = (nt - 2) * 8 + cq;
        float2 b2 = *reinterpret_cast<const float2*>(&g_bias[nt*8 + cq]);
        uint32_t hi, lo;
        split_pack(acc[nt][0] + b2.x, acc[nt][1] + b2.y, hi, lo);
        *reinterpret_cast<uint32_t*>(smc + P_VH + r0*144 + 2*dcol) = hi;
        *reinterpret_cast<uint32_t*>(smc + P_VL + r0*144 + 2*dcol) = lo;
        split_pack(acc[nt][2] + b2.x, acc[nt][3] + b2.y, hi, lo);
        *reinterpret_cast<uint32_t*>(smc + P_VH + (r0+8)*144 + 2*dcol) = hi;
        *reinterpret_cast<uint32_t*>(smc + P_VL + (r0+8)*144 + 2*dcol) = lo;
    }
    __syncwarp();

    // ldsm: A = Kp^T via trans-ldsm; B = V via trans-ldsm
    uint32_t Akh[4], Akl[4];
    {
        uint32_t aoff = (uint32_t)((16*w + (lane & 7) + ((lane & 16) >> 1)) * 48 + (lane & 8) * 2);
        ldsm_x4_t(Akh, sbase + P_KPH + aoff);
        ldsm_x4_t(Akl, sbase + P_KPL + aoff);
    }
    uint32_t Vh4[4][4], Vl4[4][4];
    {
        uint32_t boff = (uint32_t)((16*w + (lane & 15)) * 144 + ((lane >> 4) * 8) * 2);
        #pragma unroll
        for (int g2 = 0; g2 < 4; g2++) {
            ldsm_x4_t(Vh4[g2], sbase + P_VH + boff + g2 * 32);
            ldsm_x4_t(Vl4[g2], sbase + P_VL + boff + g2 * 32);
        }
    }
    // S-partial: 3-term split MMA (Kh*Vh + Kh*Vl + Kl*Vh)
    float cs[8][4];
    #pragma unroll
    for (int nt = 0; nt < 8; nt++)
        #pragma unroll
        for (int i = 0; i < 4; i++) cs[nt][i] = 0.f;
    #pragma unroll
    for (int nt = 0; nt < 8; nt++) {
        int g2 = nt >> 1, sel = (nt & 1) * 2;
        mma_f16(cs[nt], Akh, &Vh4[g2][sel]);
        mma_f16(cs[nt], Akh, &Vl4[g2][sel]);
        mma_f16(cs[nt], Akl, &Vh4[g2][sel]);
    }
    __syncthreads();   // all panel reads done -> Sred may alias

    // per-warp partial S -> Sred[w][16][64], fixed-order combine
    float* Sred = reinterpret_cast<float*>(smc);
    {
        int f0 = lane >> 2;
        #pragma unroll
        for (int nt = 0; nt < 8; nt++) {
            int dd = nt * 8 + cq;
            *reinterpret_cast<float2*>(&Sred[w*1024 + f0*64 + dd])     = make_float2(cs[nt][0], cs[nt][1]);
            *reinterpret_cast<float2*>(&Sred[w*1024 + (f0+8)*64 + dd]) = make_float2(cs[nt][2], cs[nt][3]);
        }
    }
    __syncthreads();
    #pragma unroll
    for (int i = 0; i < 4; i++) {
        int slot = tid + i * 256;
        float s = 0.f;
        #pragma unroll
        for (int ww = 0; ww < 8; ww++) s += Sred[ww*1024 + slot];
        g_Spart[(size_t)tile * (NFEAT*DH) + slot] = s;
    }
}

// ============================================================
// reduce: S[b][f][d] = sum over 64 tiles. 4 threads per (b,fd).
// ============================================================
__global__ __launch_bounds__(256) void reduce_kernel() {
    __shared__ float partial[4][64];
    const int tid = threadIdx.x;
    const int fdl  = tid & 63;
    const int part = tid >> 6;
    const int b      = blockIdx.x >> 4;
    const int fdbase = (blockIdx.x & 15) * 64;
    const int fd     = fdbase + fdl;

    const float* bs = g_Spart + (size_t)b * 64 * (NFEAT * DH) + fd;
    float s = 0.f;
    #pragma unroll
    for (int tt = 0; tt < 16; tt++)
        s += bs[(size_t)(part * 16 + tt) * (NFEAT * DH)];
    partial[part][fdl] = s;
    __syncthreads();
    if (part == 0) {
        float r = ((partial[0][fdl] + partial[1][fdl]) +
                   (partial[2][fdl] + partial[3][fdl]));
        g_S[b * (NFEAT * DH) + fd] = r;
    }
}

// ============================================================
// phase 2: y[t][d] = sum_f qP[t][f] * S[b][f][d]
// ============================================================
__global__ __launch_bounds__(128) void phase2_kernel(float* __restrict__ y) {
    __shared__ float Ss[NFEAT * DH];    // 4 KB
    __shared__ float qs[32][20];        // 2.5 KB
    const int tid  = threadIdx.x;
    const int lane = tid & 31;
    const int wp   = tid >> 5;
    const int t0   = blockIdx.x * 32;
    const int b    = t0 / TLEN;

    #pragma unroll
    for (int i = 0; i < 8; i++) Ss[tid + i * 128] = g_S[b * (NFEAT * DH) + tid + i * 128];
    {
        int idx = tid;
        float4 v = *reinterpret_cast<const float4*>(g_qP + (size_t)t0 * NFEAT + idx * 4);
        *reinterpret_cast<float4*>(&qs[idx >> 2][(idx & 3) * 4]) = v;
    }
    __syncthreads();

    float2 Sreg[NFEAT];
    #pragma unroll
    for (int f = 0; f < NFEAT; f++)
        Sreg[f] = *reinterpret_cast<const float2*>(&Ss[f * DH + 2 * lane]);

    #pragma unroll
    for (int it = 0; it < 8; it++) {
        int tok = wp * 8 + it;
        const float4* qv = reinterpret_cast<const float4*>(qs[tok]);
        float2 o = make_float2(0.f, 0.f);
        #pragma unroll
        for (int j = 0; j < 4; j++) {
            float4 q4 = qv[j];
            o.x = fmaf(q4.x, Sreg[4*j + 0].x, o.x); o.y = fmaf(q4.x, Sreg[4*j + 0].y, o.y);
            o.x = fmaf(q4.y, Sreg[4*j + 1].x, o.x); o.y = fmaf(q4.y, Sreg[4*j + 1].y, o.y);
            o.x = fmaf(q4.z, Sreg[4*j + 2].x, o.x); o.y = fmaf(q4.z, Sreg[4*j + 2].y, o.y);
            o.x = fmaf(q4.w, Sreg[4*j + 3].x, o.x); o.y = fmaf(q4.w, Sreg[4*j + 3].y, o.y);
        }
        *reinterpret_cast<float2*>(y + (size_t)(t0 + tok) * DH + 2 * lane) = o;
    }
}

// ============================================================
extern "C" void kernel_launch(void* const* d_in, const int* in_sizes, int n_in,
                              void* d_out, int out_size) {
    (void)in_sizes; (void)n_in; (void)out_size;
    const float* x  = (const float*)d_in[0];
    const float* w  = (const float*)d_in[1];
    const float* Wq = (const float*)d_in[2];
    const float* bq = (const float*)d_in[3];
    const float* Wk = (const float*)d_in[4];
    const float* bk = (const float*)d_in[5];
    const float* Wv = (const float*)d_in[6];
    const float* bv = (const float*)d_in[7];
    float* y = (float*)d_out;

    static int attr_set = 0;
    if (!attr_set) {
        cudaFuncSetAttribute(phase1_kernel, cudaFuncAttributeMaxDynamicSharedMemorySize, DYN_BYTES);
        attr_set = 1;
    }

    prep_kernel<<<(EMB * NJ + 255) / 256, 256>>>(w, Wq, bq, Wk, bk, Wv, bv);
    phase1_kernel<<<NTILE, 256, DYN_BYTES>>>(x);
    reduce_kernel<<<64, 256>>>();
    phase2_kernel<<<(BATCH * TLEN) / 32, 128>>>(y);
}